// round 2
// baseline (speedup 1.0000x reference)
#include <cuda_runtime.h>
#include <math_constants.h>

#define K_LEN 1024
#define I_LEN 8192
#define DIM   128

#define NCTA 8            // DP pipeline stages (column strips)
#define TPB  256          // DP threads per CTA
#define CPT  4            // DP columns per thread
#define WSTRIP (TPB*CPT)  // 1024 columns per CTA

// Scratch (alloc-free rule: __device__ globals)
__device__ float g_C[K_LEN * I_LEN];   // 32 MB cost matrix
__device__ float g_k2[K_LEN];
__device__ float g_x2[I_LEN];
// carry slots: slot[b][r] published by CTA b = D[r][ (b+1)*WSTRIP - 1 ]
// packed as (float bits << 32) | (r+1)
__device__ unsigned long long g_carry[NCTA * K_LEN];

// ---------------------------------------------------------------------------
// packed f32x2 helpers
// ---------------------------------------------------------------------------
__device__ __forceinline__ unsigned long long pk2(float lo, float hi) {
    unsigned long long r;
    asm("mov.b64 %0, {%1, %2};" : "=l"(r) : "f"(lo), "f"(hi));
    return r;
}
__device__ __forceinline__ float2 upk2(unsigned long long v) {
    float2 r;
    asm("mov.b64 {%0, %1}, %2;" : "=f"(r.x), "=f"(r.y) : "l"(v));
    return r;
}
__device__ __forceinline__ unsigned long long ffma2(unsigned long long a,
                                                    unsigned long long b,
                                                    unsigned long long d) {
    asm("fma.rn.f32x2 %0, %1, %2, %3;" : "=l"(d) : "l"(a), "l"(b), "l"(d));
    return d;
}

// ---------------------------------------------------------------------------
// Kernel 1: squared row norms for both inputs + zero the DP carry slots.
// ---------------------------------------------------------------------------
__global__ void norms_kernel(const float* __restrict__ kern,
                             const float* __restrict__ x) {
    int gtid = blockIdx.x * blockDim.x + threadIdx.x;
    if (gtid < NCTA * K_LEN) g_carry[gtid] = 0ull;

    int warp = gtid >> 5;
    int lane = threadIdx.x & 31;
    if (warp >= K_LEN + I_LEN) return;
    const float* row = (warp < K_LEN) ? (kern + warp * DIM)
                                      : (x + (warp - K_LEN) * DIM);
    float4 v = ((const float4*)row)[lane];          // 32 lanes * 4 = 128
    float s = v.x * v.x + v.y * v.y + v.z * v.z + v.w * v.w;
#pragma unroll
    for (int off = 16; off; off >>= 1) s += __shfl_xor_sync(0xffffffffu, s, off);
    if (lane == 0) {
        if (warp < K_LEN) g_k2[warp] = s;
        else              g_x2[warp - K_LEN] = s;
    }
}

// ---------------------------------------------------------------------------
// Kernel 2: C[m][n] = max(k2[m] + x2[n] - 2 * <kern_m, x_n>, 0)
// Tiled SGEMM, inner loop on packed fma.rn.f32x2 (2 MACs per fma-pipe issue).
// ---------------------------------------------------------------------------
#define BM 64
#define BN 64
#define BK 64

__global__ __launch_bounds__(256) void cost_gemm(const float* __restrict__ A,
                                                 const float* __restrict__ B) {
    __shared__ float As[BK][BM + 4];   // transposed: As[k][m]
    __shared__ float Bs[BK][BN + 4];   // transposed: Bs[k][n]
    const int tx = threadIdx.x & 15;
    const int ty = threadIdx.x >> 4;
    const int m0 = blockIdx.y * BM;
    const int n0 = blockIdx.x * BN;
    const int t  = threadIdx.x;

    // acc2[ip][j]: packed pair over m = (ty*4 + 2*ip, ty*4 + 2*ip + 1), col j
    unsigned long long acc2[2][4];
#pragma unroll
    for (int ip = 0; ip < 2; ip++)
#pragma unroll
        for (int j = 0; j < 4; j++) acc2[ip][j] = 0ull;

    for (int k0 = 0; k0 < DIM; k0 += BK) {
#pragma unroll
        for (int i = 0; i < 4; i++) {
            int idx = t + i * 256;        // 0..1023 over 64 rows x 16 float4
            int row = idx >> 4;
            int c4  = idx & 15;
            float4 va = *(const float4*)(A + (size_t)(m0 + row) * DIM + k0 + c4 * 4);
            As[c4 * 4 + 0][row] = va.x;
            As[c4 * 4 + 1][row] = va.y;
            As[c4 * 4 + 2][row] = va.z;
            As[c4 * 4 + 3][row] = va.w;
            float4 vb = *(const float4*)(B + (size_t)(n0 + row) * DIM + k0 + c4 * 4);
            Bs[c4 * 4 + 0][row] = vb.x;
            Bs[c4 * 4 + 1][row] = vb.y;
            Bs[c4 * 4 + 2][row] = vb.z;
            Bs[c4 * 4 + 3][row] = vb.w;
        }
        __syncthreads();
#pragma unroll 16
        for (int kk = 0; kk < BK; kk++) {
            float4 av = *(const float4*)&As[kk][ty * 4];
            float4 bv = *(const float4*)&Bs[kk][tx * 4];
            unsigned long long a01 = pk2(av.x, av.y);
            unsigned long long a23 = pk2(av.z, av.w);
            unsigned long long bb0 = pk2(bv.x, bv.x);
            unsigned long long bb1 = pk2(bv.y, bv.y);
            unsigned long long bb2 = pk2(bv.z, bv.z);
            unsigned long long bb3 = pk2(bv.w, bv.w);
            acc2[0][0] = ffma2(a01, bb0, acc2[0][0]);
            acc2[0][1] = ffma2(a01, bb1, acc2[0][1]);
            acc2[0][2] = ffma2(a01, bb2, acc2[0][2]);
            acc2[0][3] = ffma2(a01, bb3, acc2[0][3]);
            acc2[1][0] = ffma2(a23, bb0, acc2[1][0]);
            acc2[1][1] = ffma2(a23, bb1, acc2[1][1]);
            acc2[1][2] = ffma2(a23, bb2, acc2[1][2]);
            acc2[1][3] = ffma2(a23, bb3, acc2[1][3]);
        }
        __syncthreads();
    }

    // unpack to scalar acc[i][j]
    float acc[4][4];
#pragma unroll
    for (int ip = 0; ip < 2; ip++)
#pragma unroll
        for (int j = 0; j < 4; j++) {
            float2 p = upk2(acc2[ip][j]);
            acc[2 * ip + 0][j] = p.x;
            acc[2 * ip + 1][j] = p.y;
        }

#pragma unroll
    for (int i = 0; i < 4; i++) {
        int m = m0 + ty * 4 + i;
        float k2 = g_k2[m];
        float4 outv;
        float* ov = (float*)&outv;
#pragma unroll
        for (int j = 0; j < 4; j++) {
            int n = n0 + tx * 4 + j;
            float cv = k2 + g_x2[n] - 2.0f * acc[i][j];
            ov[j] = fmaxf(cv, 0.0f);
        }
        *(float4*)(g_C + (size_t)m * I_LEN + n0 + tx * 4) = outv;
    }
}

// ---------------------------------------------------------------------------
// Kernel 3: DTW DP via (min,+) scan, pipelined over NCTA column strips.
// Row recurrence: D[j] = min(D[j-1] + c[j], e[j]),
//   e[j] = min(Dprev[j-1], Dprev[j]) + c[j]
// Scan operator on (C,E): (C1,E1) ⊕ (C2,E2) = (C1+C2, min(E1+C2, E2)).
// CTA b owns columns [b*WSTRIP, (b+1)*WSTRIP). Per row, the single-float
// boundary carry D[r][b*WSTRIP-1] flows b-1 -> b via release/acquire slots.
// ---------------------------------------------------------------------------
__global__ __launch_bounds__(TPB, 1) void dtw_dp(float* __restrict__ out,
                                                 int out_size) {
    __shared__ float sh_bound[TPB];
    __shared__ float shC[8];
    __shared__ float shE[8];
    __shared__ float sh_carry;
    const float INF = CUDART_INF_F;
    const int tid  = threadIdx.x;
    const int lane = tid & 31;
    const int wid  = tid >> 5;
    const int b    = blockIdx.x;
    const size_t col0 = (size_t)b * WSTRIP + (size_t)tid * CPT;

    if (b == 0)
        for (int i = tid; i < out_size; i += TPB)
            if (i > 0) out[i] = 0.0f;

    float Dp[CPT];
#pragma unroll
    for (int j = 0; j < CPT; j++) Dp[j] = INF;
    sh_bound[tid] = INF;

    float prev_left = INF;   // thread 0 only: D[r-1][strip_start-1]
    float carry_reg = INF;   // thread 0 only: polled carry for current row

    float c[CPT];
    {
        float4 v = *(const float4*)(g_C + col0);
        c[0] = v.x; c[1] = v.y; c[2] = v.z; c[3] = v.w;
    }
    __syncthreads();

    for (int r = 0; r < K_LEN; r++) {
        // --- e-phase fused with local inclusive (min,+) prefix -------------
        float dleft = (tid == 0)
                        ? ((b == 0) ? ((r == 0) ? 0.0f : INF) : prev_left)
                        : sh_bound[tid - 1];
        float pC[CPT], pE[CPT];
        pE[0] = fminf(dleft, Dp[0]) + c[0];
        pC[0] = c[0];
#pragma unroll
        for (int j = 1; j < CPT; j++) {
            float ej = fminf(Dp[j - 1], Dp[j]) + c[j];
            pE[j] = fminf(pE[j - 1] + c[j], ej);
            pC[j] = pC[j - 1] + c[j];
        }
        float Cl = pC[CPT - 1], El = pE[CPT - 1];

        // --- prefetch next row's costs (in flight across the scans) --------
        float4 nx;
        const bool have = (r + 1 < K_LEN);
        if (have)
            nx = *(const float4*)(g_C + (size_t)(r + 1) * I_LEN + col0);

        // --- warp-level inclusive scan --------------------------------------
#pragma unroll
        for (int off = 1; off < 32; off <<= 1) {
            float Cu = __shfl_up_sync(0xffffffffu, Cl, off);
            float Eu = __shfl_up_sync(0xffffffffu, El, off);
            if (lane >= off) {
                El = fminf(Eu + Cl, El);
                Cl = Cu + Cl;
            }
        }
        if (lane == 31) { shC[wid] = Cl; shE[wid] = El; }

        // --- thread 0 polls incoming carry (overlaps with barrier wait) ----
        if (tid == 0 && b > 0) {
            const unsigned long long* slot = &g_carry[(b - 1) * K_LEN + r];
            unsigned long long v;
            do {
                asm volatile("ld.global.acquire.gpu.b64 %0, [%1];"
                             : "=l"(v) : "l"(slot));
            } while ((unsigned)v != (unsigned)(r + 1));
            carry_reg = __uint_as_float((unsigned)(v >> 32));
            sh_carry = carry_reg;
        }
        __syncthreads();

        // --- cross-warp scan over 8 warp partials (redundant per warp) -----
        float Cp = shC[lane & 7];
        float Ep = shE[lane & 7];
#pragma unroll
        for (int off = 1; off < 8; off <<= 1) {
            float Cu = __shfl_up_sync(0xffffffffu, Cp, off);
            float Eu = __shfl_up_sync(0xffffffffu, Ep, off);
            if (lane >= off) {
                Ep = fminf(Eu + Cp, Ep);
                Cp = Cu + Cp;
            }
        }
        float wC, wE;
        if (wid == 0) { wC = 0.0f; wE = INF; }
        else {
            wC = __shfl_sync(0xffffffffu, Cp, wid - 1);
            wE = __shfl_sync(0xffffffffu, Ep, wid - 1);
        }
        float exC = __shfl_up_sync(0xffffffffu, Cl, 1);
        float exE = __shfl_up_sync(0xffffffffu, El, 1);
        if (lane == 0) { exC = 0.0f; exE = INF; }

        // total exclusive prefix for this thread
        float Cex = wC + exC;
        float Eex = fminf(wE + exC, exE);
        float carry_in = (b == 0) ? INF : sh_carry;
        float Din = fminf(carry_in + Cex, Eex);

        // --- apply (fully parallel) -----------------------------------------
#pragma unroll
        for (int j = 0; j < CPT; j++)
            Dp[j] = fminf(Din + pC[j], pE[j]);

        // --- publish outgoing carry ASAP ------------------------------------
        if (tid == TPB - 1 && b < NCTA - 1) {
            unsigned long long v =
                ((unsigned long long)__float_as_uint(Dp[CPT - 1]) << 32)
                | (unsigned)(r + 1);
            asm volatile("st.global.release.gpu.b64 [%0], %1;"
                         :: "l"(&g_carry[b * K_LEN + r]), "l"(v));
        }

        sh_bound[tid] = Dp[CPT - 1];
        if (tid == 0) prev_left = carry_reg;

        if (have) { c[0] = nx.x; c[1] = nx.y; c[2] = nx.z; c[3] = nx.w; }
        __syncthreads();
    }

    if (b == NCTA - 1 && tid == TPB - 1) out[0] = Dp[CPT - 1];
}

// ---------------------------------------------------------------------------
extern "C" void kernel_launch(void* const* d_in, const int* in_sizes, int n_in,
                              void* d_out, int out_size) {
    const float* kern = (const float*)d_in[0];
    const float* x    = (const float*)d_in[1];
    // defensive: resolve by element counts in case metadata order differs
    if (n_in >= 2 && in_sizes[0] == I_LEN * DIM && in_sizes[1] == K_LEN * DIM) {
        kern = (const float*)d_in[1];
        x    = (const float*)d_in[0];
    }

    int nwarp_rows = K_LEN + I_LEN;                 // 9216 rows, 1 warp each
    norms_kernel<<<(nwarp_rows + 7) / 8, 256>>>(kern, x);

    dim3 grid(I_LEN / BN, K_LEN / BM);
    cost_gemm<<<grid, 256>>>(kern, x);

    dtw_dp<<<NCTA, TPB>>>((float*)d_out, out_size);
}